// round 4
// baseline (speedup 1.0000x reference)
#include <cuda_runtime.h>
#include <math.h>

#define NNODES 100000
#define NEDGES 1600000
#define INDIM  128
#define HID    64
#define OUTDIM 10

// ---------------------------------------------------------------------------
// Device-global scratch (no allocations allowed anywhere)
// ---------------------------------------------------------------------------
__device__ float g_dis[NNODES];
__device__ float g_A[(size_t)NNODES * HID];   // xs = dis * (X @ W)
__device__ float g_C[(size_t)NNODES * HID];   // h  = post-relu activations
__device__ int   g_deg[NNODES];
__device__ int   g_rowptr[NNODES + 1];
__device__ int   g_cursor[NNODES];
__device__ int   g_csr[NEDGES];               // source node per CSR slot
__device__ int   g_bsum[128];                 // per-block scan totals

// ---------------------------------------------------------------------------
// CSR build: degree histogram -> exclusive scan -> edge fill
// edge_index arrives as int32 (harness converts int64 -> int32).
// ---------------------------------------------------------------------------
__global__ void k_zero_deg(int N) {
    int i = blockIdx.x * blockDim.x + threadIdx.x;
    if (i < N) g_deg[i] = 0;
}

__global__ void k_deg(const int* __restrict__ col, int E) {
    int e = blockIdx.x * blockDim.x + threadIdx.x;
    if (e < E) atomicAdd(&g_deg[col[e]], 1);
}

__global__ void k_dis(int N) {
    int i = blockIdx.x * blockDim.x + threadIdx.x;
    if (i < N) g_dis[i] = rsqrtf((float)(g_deg[i] + 1));  // +1 self loop
}

// Per-block inclusive scan of g_deg (1024/block); writes block-local exclusive
// prefix into g_rowptr and block total into g_bsum.
__global__ __launch_bounds__(1024) void k_scan1(int N) {
    __shared__ int s[1024];
    int i = blockIdx.x * 1024 + threadIdx.x;
    int v = (i < N) ? g_deg[i] : 0;
    s[threadIdx.x] = v;
    __syncthreads();
#pragma unroll
    for (int off = 1; off < 1024; off <<= 1) {
        int t = (threadIdx.x >= off) ? s[threadIdx.x - off] : 0;
        __syncthreads();
        s[threadIdx.x] += t;
        __syncthreads();
    }
    if (i < N) g_rowptr[i] = s[threadIdx.x] - v;  // exclusive within block
    if (threadIdx.x == 1023) g_bsum[blockIdx.x] = s[1023];
}

// Serial exclusive scan of block totals (<=128 entries; trivial, once).
__global__ void k_scan2(int nb) {
    if (threadIdx.x == 0 && blockIdx.x == 0) {
        int run = 0;
        for (int b = 0; b < nb; b++) {
            int t = g_bsum[b];
            g_bsum[b] = run;
            run += t;
        }
    }
}

__global__ void k_scan3(int N, int E) {
    int i = blockIdx.x * blockDim.x + threadIdx.x;
    if (i < N) {
        int v = g_rowptr[i] + g_bsum[i >> 10];
        g_rowptr[i] = v;
        g_cursor[i] = v;
    }
    if (i == 0) g_rowptr[N] = E;
}

__global__ void k_fill(const int* __restrict__ row,
                       const int* __restrict__ col, int E) {
    int e = blockIdx.x * blockDim.x + threadIdx.x;
    if (e < E) {
        int c = col[e];
        int p = atomicAdd(&g_cursor[c], 1);
        g_csr[p] = row[e];
    }
}

// ---------------------------------------------------------------------------
// GEMM: g_A[node] = dis[node] * (X[node] @ W)
// 128 nodes/block, 256 threads. Thread = (kt in 0..7) x (nt in 0..31),
// computes 4 nodes x 8 outputs. K in chunks of 64. X tile XOR-swizzled.
// USE_G_C: read activations from g_C instead of the X parameter.
// ---------------------------------------------------------------------------
template <int K, bool USE_G_C>
__global__ __launch_bounds__(256) void k_gemm(const float* __restrict__ X,
                                              const float* __restrict__ W,
                                              int N) {
    __shared__ float Wsm[64 * HID];
    __shared__ float Xsm[128 * 64];

    const float* __restrict__ Xp = USE_G_C ? (const float*)g_C : X;
    const int tid = threadIdx.x;
    const int kt = tid & 7;
    const int nt = tid >> 3;
    const int nodeBase = blockIdx.x * 128;

    float acc[4][8];
#pragma unroll
    for (int i = 0; i < 4; i++)
#pragma unroll
        for (int j = 0; j < 8; j++) acc[i][j] = 0.0f;

#pragma unroll
    for (int c0 = 0; c0 < K; c0 += 64) {
        __syncthreads();
        {   // W chunk: 64x64 = 1024 float4
            const float4* Wg = (const float4*)(W + (size_t)c0 * HID);
            float4* Ws4 = (float4*)Wsm;
#pragma unroll
            for (int t = 0; t < 4; t++) Ws4[tid + 256 * t] = Wg[tid + 256 * t];
        }
        {   // X tile: 128x64 = 2048 float4, swizzled
            float4* Xs4 = (float4*)Xsm;
#pragma unroll
            for (int t = 0; t < 8; t++) {
                int idx = tid + 256 * t;
                int nl = idx >> 4;
                int c4 = idx & 15;
                int node = nodeBase + nl;
                float4 v = make_float4(0.f, 0.f, 0.f, 0.f);
                if (node < N)
                    v = ((const float4*)(Xp + (size_t)node * K + c0))[c4];
                Xs4[nl * 16 + (c4 ^ ((nl & 3) << 1))] = v;
            }
        }
        __syncthreads();

#pragma unroll
        for (int c = 0; c < 64; c++) {
            float xv[4];
#pragma unroll
            for (int i = 0; i < 4; i++) {
                int nl = nt + 32 * i;
                xv[i] = Xsm[nl * 64 + (c ^ ((nl & 3) << 3))];
            }
#pragma unroll
            for (int j = 0; j < 8; j++) {
                float wv = Wsm[c * 64 + kt + 8 * j];
#pragma unroll
                for (int i = 0; i < 4; i++)
                    acc[i][j] = fmaf(xv[i], wv, acc[i][j]);
            }
        }
    }

#pragma unroll
    for (int i = 0; i < 4; i++) {
        int node = nodeBase + nt + 32 * i;
        if (node < N) {
            float d = g_dis[node];
#pragma unroll
            for (int j = 0; j < 8; j++)
                g_A[(size_t)node * HID + kt + 8 * j] = acc[i][j] * d;
        }
    }
}

// ---------------------------------------------------------------------------
// Gather + epilogue: g_C[c] = relu(dis[c] * (g_A[c] + sum_{r in N(c)} g_A[r]) + b)
// One warp per node; lane owns 2 consecutive floats (float2). Neighbor
// indices batched 32/warp via one coalesced load + shfl broadcast; 4-deep
// unroll for load-level parallelism.
// ---------------------------------------------------------------------------
__global__ __launch_bounds__(256) void k_gather(const float* __restrict__ b,
                                                int N) {
    int w = (blockIdx.x * 256 + threadIdx.x) >> 5;
    if (w >= N) return;
    int lane = threadIdx.x & 31;

    const float2* __restrict__ A2 = (const float2*)g_A;
    float2 a0 = A2[(size_t)w * 32 + lane];   // self-loop term
    float2 a1 = make_float2(0.f, 0.f);
    float2 a2 = make_float2(0.f, 0.f);
    float2 a3 = make_float2(0.f, 0.f);

    int beg = g_rowptr[w];
    int end = g_rowptr[w + 1];

    for (int i = beg; i < end; i += 32) {
        int n = end - i;
        if (n > 32) n = 32;
        int idx = (lane < n) ? g_csr[i + lane] : 0;
        int j = 0;
        for (; j + 3 < n; j += 4) {
            int r0 = __shfl_sync(0xffffffffu, idx, j);
            int r1 = __shfl_sync(0xffffffffu, idx, j + 1);
            int r2 = __shfl_sync(0xffffffffu, idx, j + 2);
            int r3 = __shfl_sync(0xffffffffu, idx, j + 3);
            float2 v0 = A2[(size_t)r0 * 32 + lane];
            float2 v1 = A2[(size_t)r1 * 32 + lane];
            float2 v2 = A2[(size_t)r2 * 32 + lane];
            float2 v3 = A2[(size_t)r3 * 32 + lane];
            a0.x += v0.x; a0.y += v0.y;
            a1.x += v1.x; a1.y += v1.y;
            a2.x += v2.x; a2.y += v2.y;
            a3.x += v3.x; a3.y += v3.y;
        }
        for (; j < n; j++) {
            int r = __shfl_sync(0xffffffffu, idx, j);
            float2 v = A2[(size_t)r * 32 + lane];
            a0.x += v.x; a0.y += v.y;
        }
    }

    float sx = a0.x + a1.x + a2.x + a3.x;
    float sy = a0.y + a1.y + a2.y + a3.y;
    float d = g_dis[w];
    float2 bb = ((const float2*)b)[lane];
    float ox = d * sx + bb.x;
    float oy = d * sy + bb.y;
    float2 o;
    o.x = ox > 0.f ? ox : 0.f;
    o.y = oy > 0.f ? oy : 0.f;
    ((float2*)g_C)[(size_t)w * 32 + lane] = o;
}

// ---------------------------------------------------------------------------
// Head: out = log_softmax(g_C @ Wl + bl). One thread per node.
// ---------------------------------------------------------------------------
__global__ __launch_bounds__(128) void k_head(const float* __restrict__ Wl,
                                              const float* __restrict__ bl,
                                              float* __restrict__ out, int N) {
    __shared__ float Ws[HID * OUTDIM];
    __shared__ float Bs[OUTDIM];
    int tid = threadIdx.x;
    for (int i = tid; i < HID * OUTDIM; i += 128) Ws[i] = Wl[i];
    if (tid < OUTDIM) Bs[tid] = bl[tid];
    __syncthreads();

    int node = blockIdx.x * 128 + tid;
    if (node >= N) return;

    float acc[OUTDIM];
#pragma unroll
    for (int o = 0; o < OUTDIM; o++) acc[o] = Bs[o];

    const float4* h4 = (const float4*)(g_C + (size_t)node * HID);
#pragma unroll
    for (int c4 = 0; c4 < 16; c4++) {
        float4 v = h4[c4];
#pragma unroll
        for (int o = 0; o < OUTDIM; o++) {
            acc[o] = fmaf(v.x, Ws[(c4 * 4 + 0) * OUTDIM + o], acc[o]);
            acc[o] = fmaf(v.y, Ws[(c4 * 4 + 1) * OUTDIM + o], acc[o]);
            acc[o] = fmaf(v.z, Ws[(c4 * 4 + 2) * OUTDIM + o], acc[o]);
            acc[o] = fmaf(v.w, Ws[(c4 * 4 + 3) * OUTDIM + o], acc[o]);
        }
    }

    float m = acc[0];
#pragma unroll
    for (int o = 1; o < OUTDIM; o++) m = fmaxf(m, acc[o]);
    float s = 0.0f;
#pragma unroll
    for (int o = 0; o < OUTDIM; o++) s += expf(acc[o] - m);
    float lse = m + logf(s);
#pragma unroll
    for (int o = 0; o < OUTDIM; o++)
        out[(size_t)node * OUTDIM + o] = acc[o] - lse;
}

// ---------------------------------------------------------------------------
extern "C" void kernel_launch(void* const* d_in, const int* in_sizes, int n_in,
                              void* d_out, int out_size) {
    const float* x = (const float*)d_in[0];
    const int* ei = (const int*)d_in[1];   // int64 in reference -> int32 here
    const float* W1 = (const float*)d_in[2];
    const float* b1 = (const float*)d_in[3];
    const float* W2 = (const float*)d_in[4];
    const float* b2 = (const float*)d_in[5];
    const float* Wl = (const float*)d_in[6];
    const float* bl = (const float*)d_in[7];
    float* out = (float*)d_out;

    int N = in_sizes[0] / INDIM;
    int E = in_sizes[1] / 2;
    const int* row = ei;
    const int* col = ei + E;

    int nbN = (N + 255) / 256;
    int nbE = (E + 255) / 256;
    int nbScan = (N + 1023) / 1024;

    // CSR build + normalization
    k_zero_deg<<<nbN, 256>>>(N);
    k_deg<<<nbE, 256>>>(col, E);
    k_dis<<<nbN, 256>>>(N);
    k_scan1<<<nbScan, 1024>>>(N);
    k_scan2<<<1, 32>>>(nbScan);
    k_scan3<<<nbN, 256>>>(N, E);
    k_fill<<<nbE, 256>>>(row, col, E);

    // Layer 1
    k_gemm<INDIM, false><<<(N + 127) / 128, 256>>>(x, W1, N);
    k_gather<<<(N * 32 + 255) / 256, 256>>>(b1, N);

    // Layer 2
    k_gemm<HID, true><<<(N + 127) / 128, 256>>>(x, W2, N);
    k_gather<<<(N * 32 + 255) / 256, 256>>>(b2, N);

    // Head + log_softmax
    k_head<<<(N + 127) / 128, 128>>>(Wl, bl, out, N);
}